// round 3
// baseline (speedup 1.0000x reference)
#include <cuda_runtime.h>

#define BB 4
#define NN 8192
#define DD 16
#define RR 32
#define HH 64
#define EE 262144

// Scratch (allocation-free: __device__ globals)
__device__ float g_P1[BB * NN * HH];   // particles @ W1[:16] + b1
__device__ float g_P2[BB * NN * HH];   // particles @ W1[16:]
__device__ float g_rel[BB * NN * RR];  // scatter-add target

// ---------------------------------------------------------------------------
// Kernel A: per-node first-layer projections + zero the rel buffer.
// One thread per (b, n). 2048 MACs/thread, 32768 threads -> trivial.
// ---------------------------------------------------------------------------
__global__ __launch_bounds__(256) void node_proj_kernel(
    const float* __restrict__ particles,
    const float* __restrict__ W1,   // [32, 64] row-major
    const float* __restrict__ b1)   // [64]
{
    __shared__ float sW1[32 * 64];
    __shared__ float sb1[64];
    for (int i = threadIdx.x; i < 32 * 64; i += 256) sW1[i] = W1[i];
    if (threadIdx.x < 64) sb1[threadIdx.x] = b1[threadIdx.x];
    __syncthreads();

    int idx = blockIdx.x * 256 + threadIdx.x;  // 0 .. B*N-1

    float x[16];
    const float4* xp = (const float4*)(particles + (size_t)idx * 16);
    #pragma unroll
    for (int c = 0; c < 4; c++) {
        float4 v = xp[c];
        x[4 * c + 0] = v.x; x[4 * c + 1] = v.y; x[4 * c + 2] = v.z; x[4 * c + 3] = v.w;
    }

    float4* P1o = (float4*)(g_P1 + (size_t)idx * 64);
    float4* P2o = (float4*)(g_P2 + (size_t)idx * 64);

    #pragma unroll
    for (int c = 0; c < 16; c++) {
        float4 acc = ((const float4*)sb1)[c];
        #pragma unroll
        for (int i = 0; i < 16; i++) {
            float4 w = ((const float4*)(sW1 + i * 64))[c];
            acc.x += x[i] * w.x; acc.y += x[i] * w.y;
            acc.z += x[i] * w.z; acc.w += x[i] * w.w;
        }
        P1o[c] = acc;
    }
    #pragma unroll
    for (int c = 0; c < 16; c++) {
        float4 acc = make_float4(0.f, 0.f, 0.f, 0.f);
        #pragma unroll
        for (int i = 0; i < 16; i++) {
            float4 w = ((const float4*)(sW1 + (16 + i) * 64))[c];
            acc.x += x[i] * w.x; acc.y += x[i] * w.y;
            acc.z += x[i] * w.z; acc.w += x[i] * w.w;
        }
        P2o[c] = acc;
    }

    // zero rel for this node
    float4* relo = (float4*)(g_rel + (size_t)idx * 32);
    #pragma unroll
    for (int c = 0; c < 8; c++) relo[c] = make_float4(0.f, 0.f, 0.f, 0.f);
}

// ---------------------------------------------------------------------------
// Kernel B: edge MLP (dominant). One thread per (edge, batch).
//   h = relu(P1[sender] + P2[receiver])          (64 adds, no matmul!)
//   rel_feat = relu(h @ W2 + b2)                 (64x32 = 2048 MACs)
//   atomicAdd rel[receiver] += rel_feat          (32 REDG)
// ---------------------------------------------------------------------------
__global__ __launch_bounds__(256) void edge_kernel(
    const int* __restrict__ senders,
    const int* __restrict__ receivers,
    const float* __restrict__ W2,   // [64, 32] row-major
    const float* __restrict__ b2)   // [32]
{
    __shared__ float sW2[64 * 32];
    __shared__ float sb2[32];
    for (int i = threadIdx.x; i < 64 * 32; i += 256) sW2[i] = W2[i];
    if (threadIdx.x < 32) sb2[threadIdx.x] = b2[threadIdx.x];
    __syncthreads();

    int e = blockIdx.x * 256 + threadIdx.x;
    int b = blockIdx.y;
    int s = senders[e];
    int r = receivers[e];

    const float4* p1 = (const float4*)(g_P1 + ((size_t)(b * NN + s)) * 64);
    const float4* p2 = (const float4*)(g_P2 + ((size_t)(b * NN + r)) * 64);

    float acc[32];
    #pragma unroll
    for (int j = 0; j < 32; j++) acc[j] = sb2[j];

    // process h in 4 blocks of 16 to keep register pressure low
    #pragma unroll
    for (int blk = 0; blk < 4; blk++) {
        float h[16];
        #pragma unroll
        for (int q = 0; q < 4; q++) {
            float4 a = p1[blk * 4 + q];
            float4 c = p2[blk * 4 + q];
            h[q * 4 + 0] = fmaxf(a.x + c.x, 0.f);
            h[q * 4 + 1] = fmaxf(a.y + c.y, 0.f);
            h[q * 4 + 2] = fmaxf(a.z + c.z, 0.f);
            h[q * 4 + 3] = fmaxf(a.w + c.w, 0.f);
        }
        #pragma unroll
        for (int i = 0; i < 16; i++) {
            const float4* w = (const float4*)(sW2 + (blk * 16 + i) * 32);
            float hv = h[i];
            #pragma unroll
            for (int j = 0; j < 8; j++) {
                float4 wv = w[j];
                acc[4 * j + 0] += hv * wv.x;
                acc[4 * j + 1] += hv * wv.y;
                acc[4 * j + 2] += hv * wv.z;
                acc[4 * j + 3] += hv * wv.w;
            }
        }
    }

    float* relp = g_rel + ((size_t)(b * NN + r)) * 32;
    #pragma unroll
    for (int j = 0; j < 32; j++) {
        atomicAdd(relp + j, fmaxf(acc[j], 0.f));
    }
}

// ---------------------------------------------------------------------------
// Kernel C: node MLP + residual. One thread per (b, n).
//   delta = relu([particles, rel] @ W3 + b3) @ W4 + b4
//   out = particles + delta
// ---------------------------------------------------------------------------
__global__ __launch_bounds__(256) void node_out_kernel(
    const float* __restrict__ particles,
    const float* __restrict__ W3,   // [48, 64]
    const float* __restrict__ b3,   // [64]
    const float* __restrict__ W4,   // [64, 16]
    const float* __restrict__ b4,   // [16]
    float* __restrict__ out)
{
    __shared__ float sW3[48 * 64];
    __shared__ float sW4[64 * 16];
    __shared__ float sb3[64];
    __shared__ float sb4[16];
    for (int i = threadIdx.x; i < 48 * 64; i += 256) sW3[i] = W3[i];
    for (int i = threadIdx.x; i < 64 * 16; i += 256) sW4[i] = W4[i];
    if (threadIdx.x < 64) sb3[threadIdx.x] = b3[threadIdx.x];
    if (threadIdx.x < 16) sb4[threadIdx.x] = b4[threadIdx.x];
    __syncthreads();

    int idx = blockIdx.x * 256 + threadIdx.x;

    float x[48];
    const float4* pp = (const float4*)(particles + (size_t)idx * 16);
    #pragma unroll
    for (int c = 0; c < 4; c++) {
        float4 v = pp[c];
        x[4 * c + 0] = v.x; x[4 * c + 1] = v.y; x[4 * c + 2] = v.z; x[4 * c + 3] = v.w;
    }
    const float4* rp = (const float4*)(g_rel + (size_t)idx * 32);
    #pragma unroll
    for (int c = 0; c < 8; c++) {
        float4 v = rp[c];
        x[16 + 4 * c + 0] = v.x; x[16 + 4 * c + 1] = v.y;
        x[16 + 4 * c + 2] = v.z; x[16 + 4 * c + 3] = v.w;
    }

    float delta[16];
    #pragma unroll
    for (int j = 0; j < 16; j++) delta[j] = sb4[j];

    // hidden layer in two halves of 32 to bound register pressure
    #pragma unroll
    for (int half = 0; half < 2; half++) {
        float t[32];
        #pragma unroll
        for (int j = 0; j < 32; j++) t[j] = sb3[half * 32 + j];

        #pragma unroll
        for (int i = 0; i < 48; i++) {
            const float4* w = (const float4*)(sW3 + i * 64 + half * 32);
            float xv = x[i];
            #pragma unroll
            for (int j = 0; j < 8; j++) {
                float4 wv = w[j];
                t[4 * j + 0] += xv * wv.x;
                t[4 * j + 1] += xv * wv.y;
                t[4 * j + 2] += xv * wv.z;
                t[4 * j + 3] += xv * wv.w;
            }
        }
        #pragma unroll
        for (int j = 0; j < 32; j++) t[j] = fmaxf(t[j], 0.f);

        #pragma unroll
        for (int i = 0; i < 32; i++) {
            const float4* w = (const float4*)(sW4 + (half * 32 + i) * 16);
            float tv = t[i];
            #pragma unroll
            for (int j = 0; j < 4; j++) {
                float4 wv = w[j];
                delta[4 * j + 0] += tv * wv.x;
                delta[4 * j + 1] += tv * wv.y;
                delta[4 * j + 2] += tv * wv.z;
                delta[4 * j + 3] += tv * wv.w;
            }
        }
    }

    float4* outp = (float4*)(out + (size_t)idx * 16);
    #pragma unroll
    for (int c = 0; c < 4; c++) {
        outp[c] = make_float4(x[4 * c + 0] + delta[4 * c + 0],
                              x[4 * c + 1] + delta[4 * c + 1],
                              x[4 * c + 2] + delta[4 * c + 2],
                              x[4 * c + 3] + delta[4 * c + 3]);
    }
}

extern "C" void kernel_launch(void* const* d_in, const int* in_sizes, int n_in,
                              void* d_out, int out_size)
{
    const float* particles = (const float*)d_in[0];
    const int*   senders   = (const int*)d_in[1];
    const int*   receivers = (const int*)d_in[2];
    const float* W1 = (const float*)d_in[3];
    const float* b1 = (const float*)d_in[4];
    const float* W2 = (const float*)d_in[5];
    const float* b2 = (const float*)d_in[6];
    const float* W3 = (const float*)d_in[7];
    const float* b3 = (const float*)d_in[8];
    const float* W4 = (const float*)d_in[9];
    const float* b4 = (const float*)d_in[10];
    float* out = (float*)d_out;

    node_proj_kernel<<<(BB * NN) / 256, 256>>>(particles, W1, b1);

    dim3 egrid(EE / 256, BB);
    edge_kernel<<<egrid, 256>>>(senders, receivers, W2, b2);

    node_out_kernel<<<(BB * NN) / 256, 256>>>(particles, W3, b3, W4, b4, out);
}